// round 17
// baseline (speedup 1.0000x reference)
#include <cuda_runtime.h>
#include <cuda_bf16.h>
#include <math.h>
#include <stdint.h>

#define F_  1024
#define H_  16
#define D_  18
#define P_  64
#define B_  128
#define T_  8192
#define C3F 3072
#define NC  23
#define MH  4096

typedef __nv_bfloat16 bf16;
typedef unsigned long long u64;

__device__ float g_qln[2][F_];
__device__ float g_qhp[2][8][F_];
__device__ __align__(16) float g_wkeff[2][H_ * F_];
__device__ float g_bkeff[2][H_];
__device__ float g_z[(size_t)T_ * F_];
__device__ float g_kv[(size_t)T_ * F_];
__device__ float g_p2[B_ * F_];
__device__ float g_hid[B_ * MH];
__device__ __align__(16) bf16 g_mx_h[(size_t)H_ * T_ * F_], g_mx_l[(size_t)H_ * T_ * F_];
__device__ __align__(16) bf16 g_pooled_h[(size_t)T_ * F_], g_pooled_l[(size_t)T_ * F_];
__device__ __align__(16) bf16 g_mx2_h[H_ * B_ * F_], g_mx2_l[H_ * B_ * F_];
__device__ __align__(16) bf16 g_pooled2_h[B_ * F_], g_pooled2_l[B_ * F_];
__device__ __align__(16) bf16 g_p2ln_h[B_ * F_], g_p2ln_l[B_ * F_];
__device__ __align__(16) bf16 g_wvT_h[F_ * F_],  g_wvT_l[F_ * F_];
__device__ __align__(16) bf16 g_chowT_h[F_ * F_], g_chowT_l[F_ * F_];
__device__ __align__(16) bf16 g_wv2T_h[F_ * F_], g_wv2T_l[F_ * F_];
__device__ __align__(16) bf16 g_towT_h[F_ * F_], g_towT_l[F_ * F_];
__device__ __align__(16) bf16 g_w1T_h[MH * F_],  g_w1T_l[MH * F_];

__device__ __forceinline__ uint32_t smem_u32(const void* p) {
    uint32_t a;
    asm("{ .reg .u64 t; cvta.to.shared.u64 t, %1; cvt.u32.u64 %0, t; }" : "=r"(a) : "l"(p));
    return a;
}
__device__ __forceinline__ void ldsm4(uint32_t& r0, uint32_t& r1, uint32_t& r2, uint32_t& r3, uint32_t a) {
    asm volatile("ldmatrix.sync.aligned.m8n8.x4.shared.b16 {%0,%1,%2,%3}, [%4];"
        : "=r"(r0), "=r"(r1), "=r"(r2), "=r"(r3) : "r"(a));
}
__device__ __forceinline__ void mma_bf16(float* c, const uint32_t* a, uint32_t b0, uint32_t b1) {
    asm volatile("mma.sync.aligned.m16n8k16.row.col.f32.bf16.bf16.f32 "
        "{%0,%1,%2,%3},{%4,%5,%6,%7},{%8,%9},{%0,%1,%2,%3};"
        : "+f"(c[0]), "+f"(c[1]), "+f"(c[2]), "+f"(c[3])
        : "r"(a[0]), "r"(a[1]), "r"(a[2]), "r"(a[3]), "r"(b0), "r"(b1));
}
#define CP16(dst, src) asm volatile("cp.async.cg.shared.global [%0], [%1], 16;" :: "r"(dst), "l"(src))
#define CPCOMMIT()     asm volatile("cp.async.commit_group;" ::: "memory")
#define CPWAIT(n)      asm volatile("cp.async.wait_group %0;" :: "n"(n) : "memory")
#define FMA2(d, a, b)  asm("fma.rn.f32x2 %0, %1, %2, %0;" : "+l"(d) : "l"(a), "l"(b))

__device__ __forceinline__ void sp2(float v0, float v1, uint32_t& h, uint32_t& l) {
    bf16 h0 = __float2bfloat16(v0), h1 = __float2bfloat16(v1);
    bf16 l0 = __float2bfloat16(v0 - __bfloat162float(h0));
    bf16 l1 = __float2bfloat16(v1 - __bfloat162float(h1));
    h = ((uint32_t)__bfloat16_as_ushort(h1) << 16) | __bfloat16_as_ushort(h0);
    l = ((uint32_t)__bfloat16_as_ushort(l1) << 16) | __bfloat16_as_ushort(l0);
}
__device__ __forceinline__ float block_sum_256(float v, float* red) {
    #pragma unroll
    for (int o = 16; o; o >>= 1) v += __shfl_xor_sync(0xffffffffu, v, o);
    int w = threadIdx.x >> 5;
    if ((threadIdx.x & 31) == 0) red[w] = v;
    __syncthreads();
    float s = red[0];
    #pragma unroll
    for (int i = 1; i < 8; i++) s += red[i];
    __syncthreads();
    return s;
}

// ---------------- weight transpose + split ----------------
__global__ __launch_bounds__(256) void k_trsplit(const float* __restrict__ src, int lds, int ofs,
                                                 bf16* __restrict__ dh, bf16* __restrict__ dl) {
    __shared__ float t[32][33];
    int k0 = blockIdx.x * 32, n0 = blockIdx.y * 32;
    int tx = threadIdx.x & 31, ty = threadIdx.x >> 5;
    #pragma unroll
    for (int j = 0; j < 4; j++)
        t[ty + j * 8][tx] = src[(size_t)(k0 + ty + j * 8) * lds + ofs + n0 + tx];
    __syncthreads();
    #pragma unroll
    for (int j = 0; j < 4; j++) {
        int r = ty + j * 8;
        float v = t[tx][r];
        bf16 h = __float2bfloat16(v);
        bf16 l = __float2bfloat16(v - __bfloat162float(h));
        size_t o = (size_t)(n0 + r) * F_ + k0 + tx;
        dh[o] = h; dl[o] = l;
    }
}

// ---------------- cp.async 3-stage split-bf16 GEMM (proven) ----------------
#define STG_B 18432
__global__ __launch_bounds__(256) void k_mma(
    const bf16* __restrict__ Ah, const bf16* __restrict__ Al, long long sA,
    const bf16* __restrict__ Bh, const bf16* __restrict__ Bl, long long sB,
    const float* __restrict__ bias, long long sBias,
    float* __restrict__ Cf, bf16* __restrict__ Ch, bf16* __restrict__ Cl,
    int ldc, long long sC, int mode)
{
    extern __shared__ bf16 s[];
    int z = blockIdx.z;
    Ah += (size_t)z * sA; Al += (size_t)z * sA;
    Bh += (size_t)z * sB; Bl += (size_t)z * sB;
    const float* bz = bias + (size_t)z * sBias;
    const int tM = blockIdx.y * 128, tN = blockIdx.x * 64;
    const int t = threadIdx.x, wid = t >> 5, lane = t & 31;
    const int m_idx = wid >> 1, n_idx = wid & 1;
    uint32_t sbase = smem_u32(s);

    const int ar = t >> 1, aseg = t & 1;
    const bf16* agh = Ah + (size_t)(tM + ar) * F_ + aseg * 8;
    const bf16* agl = Al + (size_t)(tM + ar) * F_ + aseg * 8;
    const uint32_t adst = ar * 48 + aseg * 16;
    const int br = (t & 127) >> 1, bseg = t & 1;
    const bf16* bgp = ((t < 128) ? Bh : Bl) + (size_t)(tN + br) * F_ + bseg * 8;
    const uint32_t bdst = 12288 + ((t >= 128) ? 3072u : 0u) + br * 48 + bseg * 16;

    uint32_t oA[2], oB[2];
    #pragma unroll
    for (int ti = 0; ti < 2; ti++) {
        int r = m_idx * 32 + ti * 16 + (lane & 15);
        oA[ti] = r * 48 + (lane >> 4) * 16;
    }
    #pragma unroll
    for (int gi = 0; gi < 2; gi++) {
        int mtx = lane >> 3;
        int nr = n_idx * 32 + gi * 16 + (mtx >> 1) * 8 + (lane & 7);
        oB[gi] = 12288 + nr * 48 + (mtx & 1) * 16;
    }

    float acc[2][4][4];
    #pragma unroll
    for (int i = 0; i < 2; i++)
        #pragma unroll
        for (int j = 0; j < 4; j++)
            #pragma unroll
            for (int k = 0; k < 4; k++) acc[i][j][k] = 0.f;

    #pragma unroll
    for (int sp = 0; sp < 2; sp++) {
        uint32_t sb = sbase + sp * STG_B;
        CP16(sb + adst, agh + sp * 16);
        CP16(sb + 6144 + adst, agl + sp * 16);
        CP16(sb + bdst, bgp + sp * 16);
        CPCOMMIT();
    }

    for (int c = 0; c < 64; c++) {
        if (c < 62) {
            int nc = c + 2;
            uint32_t sb = sbase + (nc % 3) * STG_B;
            CP16(sb + adst, agh + nc * 16);
            CP16(sb + 6144 + adst, agl + nc * 16);
            CP16(sb + bdst, bgp + nc * 16);
            CPCOMMIT();
            CPWAIT(2);
        } else if (c == 62) CPWAIT(1);
        else CPWAIT(0);
        __syncthreads();

        uint32_t sb = sbase + (c % 3) * STG_B;
        uint32_t Ahf[2][4], Alf[2][4], Bhf[2][4], Blf[2][4];
        #pragma unroll
        for (int ti = 0; ti < 2; ti++) {
            ldsm4(Ahf[ti][0], Ahf[ti][1], Ahf[ti][2], Ahf[ti][3], sb + oA[ti]);
            ldsm4(Alf[ti][0], Alf[ti][1], Alf[ti][2], Alf[ti][3], sb + 6144 + oA[ti]);
        }
        #pragma unroll
        for (int gi = 0; gi < 2; gi++) {
            ldsm4(Bhf[gi][0], Bhf[gi][1], Bhf[gi][2], Bhf[gi][3], sb + oB[gi]);
            ldsm4(Blf[gi][0], Blf[gi][1], Blf[gi][2], Blf[gi][3], sb + 3072 + oB[gi]);
        }
        #pragma unroll
        for (int ti = 0; ti < 2; ti++)
            #pragma unroll
            for (int gi = 0; gi < 2; gi++)
                #pragma unroll
                for (int sub = 0; sub < 2; sub++) {
                    int tn = gi * 2 + sub;
                    mma_bf16(acc[ti][tn], Ahf[ti], Bhf[gi][2 * sub], Bhf[gi][2 * sub + 1]);
                    mma_bf16(acc[ti][tn], Ahf[ti], Blf[gi][2 * sub], Blf[gi][2 * sub + 1]);
                    mma_bf16(acc[ti][tn], Alf[ti], Bhf[gi][2 * sub], Bhf[gi][2 * sub + 1]);
                }
        __syncthreads();
    }

    const int g = lane >> 2, tg = lane & 3;
    #pragma unroll
    for (int ti = 0; ti < 2; ti++) {
        int r0 = tM + m_idx * 32 + ti * 16 + g;
        #pragma unroll
        for (int tn = 0; tn < 4; tn++) {
            int col = tN + n_idx * 32 + tn * 8 + tg * 2;
            float b0 = bz[col], b1 = bz[col + 1];
            float v0 = acc[ti][tn][0] + b0, v1 = acc[ti][tn][1] + b1;
            float v2 = acc[ti][tn][2] + b0, v3 = acc[ti][tn][3] + b1;
            if (mode == 1) {
                v0 = 0.5f * v0 * (1.f + erff(v0 * 0.70710678118654752f));
                v1 = 0.5f * v1 * (1.f + erff(v1 * 0.70710678118654752f));
                v2 = 0.5f * v2 * (1.f + erff(v2 * 0.70710678118654752f));
                v3 = 0.5f * v3 * (1.f + erff(v3 * 0.70710678118654752f));
            }
            if (mode == 2) {
                uint32_t h, l;
                sp2(v0, v1, h, l);
                *(uint32_t*)(Ch + (size_t)z * sC + (size_t)r0 * ldc + col) = h;
                *(uint32_t*)(Cl + (size_t)z * sC + (size_t)r0 * ldc + col) = l;
                sp2(v2, v3, h, l);
                *(uint32_t*)(Ch + (size_t)z * sC + (size_t)(r0 + 8) * ldc + col) = h;
                *(uint32_t*)(Cl + (size_t)z * sC + (size_t)(r0 + 8) * ldc + col) = l;
            } else {
                float* Cz = Cf + (size_t)z * sC;
                *(float2*)(Cz + (size_t)r0 * ldc + col)       = make_float2(v0, v1);
                *(float2*)(Cz + (size_t)(r0 + 8) * ldc + col) = make_float2(v2, v3);
            }
        }
    }
}

// ---------------- merged query LayerNorm ----------------
__global__ __launch_bounds__(256) void k_lnq(const float* __restrict__ chq, const float* __restrict__ clq,
                                             const float* __restrict__ g0, const float* __restrict__ b0,
                                             const float* __restrict__ g1, const float* __restrict__ b1) {
    __shared__ float red[8];
    int which = blockIdx.x;
    const float* src = which ? clq : chq;
    const float* g = which ? g1 : g0;
    const float* b = which ? b1 : b0;
    float* dst = g_qln[which];
    int tid = threadIdx.x;
    float4 v = ((const float4*)src)[tid];
    float m = block_sum_256(v.x + v.y + v.z + v.w, red) * (1.f / 1024.f);
    float dx = v.x - m, dy = v.y - m, dz = v.z - m, dw = v.w - m;
    float var = block_sum_256(dx*dx + dy*dy + dz*dz + dw*dw, red) * (1.f / 1024.f);
    float rs = rsqrtf(var + 1e-5f);
    float4 gv = ((const float4*)g)[tid], bv = ((const float4*)b)[tid];
    float4 o;
    o.x = dx * rs * gv.x + bv.x; o.y = dy * rs * gv.y + bv.y;
    o.z = dz * rs * gv.z + bv.z; o.w = dw * rs * gv.w + bv.w;
    ((float4*)dst)[tid] = o;
}

__global__ __launch_bounds__(256) void k_ln_split(const float* __restrict__ src,
                                                  const float* __restrict__ g,
                                                  const float* __restrict__ b,
                                                  bf16* __restrict__ dh, bf16* __restrict__ dl) {
    __shared__ float red[8];
    size_t row = blockIdx.x;
    int tid = threadIdx.x;
    float4 v = ((const float4*)src)[row * 256 + tid];
    float m = block_sum_256(v.x + v.y + v.z + v.w, red) * (1.f / 1024.f);
    float dx = v.x - m, dy = v.y - m, dz = v.z - m, dw = v.w - m;
    float var = block_sum_256(dx*dx + dy*dy + dz*dz + dw*dw, red) * (1.f / 1024.f);
    float rs = rsqrtf(var + 1e-5f);
    float4 gv = ((const float4*)g)[tid], bv = ((const float4*)b)[tid];
    float o0 = dx * rs * gv.x + bv.x, o1 = dy * rs * gv.y + bv.y;
    float o2 = dz * rs * gv.z + bv.z, o3 = dw * rs * gv.w + bv.w;
    uint2 uh, ul;
    sp2(o0, o1, uh.x, ul.x);
    sp2(o2, o3, uh.y, ul.y);
    ((uint2*)dh)[row * 256 + tid] = uh;
    ((uint2*)dl)[row * 256 + tid] = ul;
}

// ---------------- qh partials: split-K ----------------
__global__ __launch_bounds__(128) void k_qh(const float* __restrict__ chw, const float* __restrict__ tw) {
    int side = blockIdx.y, ks = blockIdx.z;
    const float* W = side ? tw : chw;
    const float* q = g_qln[side] + ks * 128;
    __shared__ float qs[128];
    int tid = threadIdx.x;
    qs[tid] = q[tid];
    __syncthreads();
    int j = blockIdx.x * 128 + tid;
    const float* Wp = W + (size_t)(ks * 128) * C3F + j;
    float a0 = 0.f, a1 = 0.f, a2 = 0.f, a3 = 0.f;
    for (int f = 0; f < 128; f += 4) {
        a0 = fmaf(qs[f],     Wp[(size_t)f * C3F], a0);
        a1 = fmaf(qs[f + 1], Wp[(size_t)(f + 1) * C3F], a1);
        a2 = fmaf(qs[f + 2], Wp[(size_t)(f + 2) * C3F], a2);
        a3 = fmaf(qs[f + 3], Wp[(size_t)(f + 3) * C3F], a3);
    }
    g_qhp[side][ks][j] = a0 + a1 + a2 + a3;
}

// ---------------- fold (reduces qh partials inline) ----------------
__global__ __launch_bounds__(128) void k_fold(const float* __restrict__ chw, const float* __restrict__ chb,
                                              const float* __restrict__ tw, const float* __restrict__ tb) {
    int side = blockIdx.y, f0 = blockIdx.x * 2, tid = threadIdx.x;
    const float* W  = side ? tw : chw;
    const float* bb = side ? tb : chb;
    __shared__ float qh[F_];
    __shared__ float wrow[2][F_];
    for (int i = tid; i < F_; i += 128) {
        float s = bb[i];
        #pragma unroll
        for (int ks = 0; ks < 8; ks++) s += g_qhp[side][ks][i];
        qh[i] = s;
    }
    for (int i = tid; i < F_; i += 128) {
        wrow[0][i] = W[(size_t)f0 * C3F + F_ + i];
        wrow[1][i] = W[(size_t)(f0 + 1) * C3F + F_ + i];
    }
    __syncthreads();
    int h = tid >> 3, i8 = tid & 7;
    #pragma unroll
    for (int r = 0; r < 2; r++) {
        float s = 0.f;
        #pragma unroll
        for (int d = 0; d < 8; d++) s += wrow[r][h * 64 + i8 * 8 + d] * qh[h * 64 + i8 * 8 + d];
        s += __shfl_down_sync(0xffffffffu, s, 4, 8);
        s += __shfl_down_sync(0xffffffffu, s, 2, 8);
        s += __shfl_down_sync(0xffffffffu, s, 1, 8);
        if (i8 == 0) g_wkeff[side][h * F_ + f0 + r] = s;
    }
    if (f0 == 0 && tid < H_) {
        float bs = 0.f;
        for (int d = 0; d < 64; d++) bs += bb[F_ + tid * 64 + d] * qh[tid * 64 + d];
        g_bkeff[side][tid] = bs;
    }
}

// ---------------- fused stage-1 v4: 512 threads, quarter-col score warps ----------------
#define SMEM_MAIN (D_ * F_ * 4 + 4 * 288 * 4 + 288 * 4 + 288 * 8)
__global__ __launch_bounds__(512, 2) void k_main(const float* __restrict__ x) {
    extern __shared__ float sm[];
    float* xs   = sm;                    // [18][1024]
    float* part = xs + D_ * F_;          // [4][288]
    float* sc   = part + 4 * 288;        // [288]
    u64* attnP  = (u64*)(sc + 288);      // [k*16+h]

    int p = blockIdx.x, b = blockIdx.y, tid = threadIdx.x;
    int t = b * P_ + p;
    int w = tid >> 5, lane = tid & 31;
    int cq = w & 3, hg = w >> 2;         // quarter-col, head-group of 4

    u64 wk[4][4];
    #pragma unroll
    for (int hh = 0; hh < 4; hh++) {
        const u64* wr = (const u64*)(g_wkeff[0] + (hg * 4 + hh) * F_ + cq * 256);
        #pragma unroll
        for (int i = 0; i < 4; i++) wk[hh][i] = wr[lane + i * 32];
    }

    const float2* xg = (const float2*)x;
    #pragma unroll
    for (int k = 0; k < D_; k++)
        ((float2*)xs)[k * 512 + tid] = xg[((size_t)(b * D_ + k) * P_ + p) * 512 + tid];
    __syncthreads();

    for (int k = 0; k < D_; k++) {
        const u64* xr = (const u64*)(xs + k * F_ + cq * 256);
        u64 xv[4];
        #pragma unroll
        for (int i = 0; i < 4; i++) xv[i] = xr[lane + i * 32];
        #pragma unroll
        for (int hh = 0; hh < 4; hh++) {
            u64 s2 = 0;
            #pragma unroll
            for (int i = 0; i < 4; i++) FMA2(s2, xv[i], wk[hh][i]);
            float s = __uint_as_float((unsigned)s2) + __uint_as_float((unsigned)(s2 >> 32));
            #pragma unroll
            for (int o = 16; o; o >>= 1) s += __shfl_xor_sync(0xffffffffu, s, o);
            if (lane == 0) part[cq * 288 + (hg * 4 + hh) * D_ + k] = s;
        }
    }
    __syncthreads();

    for (int pair = tid; pair < 288; pair += 512)
        sc[pair] = (part[pair] + part[288 + pair] + part[576 + pair] + part[864 + pair]
                    + g_bkeff[0][pair / D_]) * 0.125f;
    __syncthreads();

    if (tid < H_) {
        int h = tid;
        float mx = -1e30f;
        #pragma unroll
        for (int k = 0; k < D_; k++) mx = fmaxf(mx, sc[h * D_ + k]);
        float e[D_], ss = 0.f;
        #pragma unroll
        for (int k = 0; k < D_; k++) { e[k] = expf(sc[h * D_ + k] - mx); ss += e[k]; }
        float inv = 1.f / ss;
        #pragma unroll
        for (int k = 0; k < D_; k++) {
            unsigned u = __float_as_uint(e[k] * inv);
            attnP[k * H_ + h] = ((u64)u << 32) | u;
        }
    }
    __syncthreads();

    u64 acc[H_];
    #pragma unroll
    for (int h = 0; h < H_; h++) acc[h] = 0;
    #pragma unroll
    for (int k = 0; k < D_; k++) {
        u64 xv = ((const u64*)xs)[k * 512 + tid];
        const u64* ap = attnP + k * H_;
        #pragma unroll
        for (int h = 0; h < H_; h++) FMA2(acc[h], ap[h], xv);
    }
    #pragma unroll
    for (int h = 0; h < H_; h++) {
        float f0 = __uint_as_float((unsigned)acc[h]);
        float f1 = __uint_as_float((unsigned)(acc[h] >> 32));
        uint32_t uh, ul;
        sp2(f0, f1, uh, ul);
        size_t o = ((size_t)h * T_ + t) * 512 + tid;
        ((uint32_t*)g_mx_h)[o] = uh;
        ((uint32_t*)g_mx_l)[o] = ul;
    }
}

// ---------------- kv = ln(ln(z, cn), pnp) ----------------
__global__ __launch_bounds__(256) void k_lnln(const float* __restrict__ g1, const float* __restrict__ b1,
                                              const float* __restrict__ g2, const float* __restrict__ b2) {
    __shared__ float red[8];
    size_t row = blockIdx.x;
    int tid = threadIdx.x;
    float4 v = ((const float4*)g_z)[row * 256 + tid];
    float m = block_sum_256(v.x + v.y + v.z + v.w, red) * (1.f / 1024.f);
    float dx = v.x - m, dy = v.y - m, dz = v.z - m, dw = v.w - m;
    float var = block_sum_256(dx*dx + dy*dy + dz*dz + dw*dw, red) * (1.f / 1024.f);
    float rs = rsqrtf(var + 1e-5f);
    float4 g1v = ((const float4*)g1)[tid], b1v = ((const float4*)b1)[tid];
    float yx = dx * rs * g1v.x + b1v.x, yy = dy * rs * g1v.y + b1v.y;
    float yz = dz * rs * g1v.z + b1v.z, yw = dw * rs * g1v.w + b1v.w;
    float m2 = block_sum_256(yx + yy + yz + yw, red) * (1.f / 1024.f);
    float ex = yx - m2, ey = yy - m2, ez = yz - m2, ew = yw - m2;
    float var2 = block_sum_256(ex*ex + ey*ey + ez*ez + ew*ew, red) * (1.f / 1024.f);
    float rs2 = rsqrtf(var2 + 1e-5f);
    float4 g2v = ((const float4*)g2)[tid], b2v = ((const float4*)b2)[tid];
    float4 o;
    o.x = ex * rs2 * g2v.x + b2v.x; o.y = ey * rs2 * g2v.y + b2v.y;
    o.z = ez * rs2 * g2v.z + b2v.z; o.w = ew * rs2 * g2v.w + b2v.w;
    ((float4*)g_kv)[row * 256 + tid] = o;
}

// ---------------- stage-2 fused v2 ----------------
__global__ __launch_bounds__(256) void k_sc2mix() {
    __shared__ float rows[4 * F_];
    __shared__ float sc[H_ * P_];
    int b = blockIdx.x, tid = threadIdx.x, w = tid >> 5, lane = tid & 31;

    int h0 = 2 * w, h1 = 2 * w + 1;
    ulonglong2 wk0[8], wk1[8];
    const ulonglong2* wr0 = (const ulonglong2*)(g_wkeff[1] + h0 * F_);
    const ulonglong2* wr1 = (const ulonglong2*)(g_wkeff[1] + h1 * F_);
    #pragma unroll
    for (int i = 0; i < 8; i++) { wk0[i] = wr0[lane + i * 32]; wk1[i] = wr1[lane + i * 32]; }
    float bk0 = g_bkeff[1][h0], bk1 = g_bkeff[1][h1];

    for (int pb = 0; pb < 16; pb++) {
        #pragma unroll
        for (int r = 0; r < 4; r++)
            ((float4*)rows)[r * 256 + tid] =
                ((const float4*)g_kv)[(size_t)(b * P_ + pb * 4 + r) * 256 + tid];
        __syncthreads();
        #pragma unroll
        for (int r = 0; r < 4; r++) {
            const ulonglong2* xr = (const ulonglong2*)(rows + r * F_);
            u64 s0 = 0, s1 = 0;
            #pragma unroll
            for (int i = 0; i < 8; i++) {
                ulonglong2 xv = xr[lane + i * 32];
                FMA2(s0, xv.x, wk0[i].x); FMA2(s0, xv.y, wk0[i].y);
                FMA2(s1, xv.x, wk1[i].x); FMA2(s1, xv.y, wk1[i].y);
            }
            float a0 = __uint_as_float((unsigned)s0) + __uint_as_float((unsigned)(s0 >> 32));
            float a1 = __uint_as_float((unsigned)s1) + __uint_as_float((unsigned)(s1 >> 32));
            #pragma unroll
            for (int o = 16; o; o >>= 1) {
                a0 += __shfl_xor_sync(0xffffffffu, a0, o);
                a1 += __shfl_xor_sync(0xffffffffu, a1, o);
            }
            if (lane == 0) {
                int p = pb * 4 + r;
                sc[h0 * P_ + p] = (a0 + bk0) * 0.125f;
                sc[h1 * P_ + p] = (a1 + bk1) * 0.125f;
            }
        }
        __syncthreads();
    }

    if (tid < H_) {
        int h = tid;
        float mx = -1e30f;
        for (int p = 0; p < P_; p++) mx = fmaxf(mx, sc[h * P_ + p]);
        float ss = 0.f;
        for (int p = 0; p < P_; p++) { float e = expf(sc[h * P_ + p] - mx); sc[h * P_ + p] = e; ss += e; }
        float inv = 1.f / ss;
        for (int p = 0; p < P_; p++) sc[h * P_ + p] *= inv;
    }
    __syncthreads();

    float4 acc[H_];
    #pragma unroll
    for (int h = 0; h < H_; h++) acc[h] = make_float4(0.f, 0.f, 0.f, 0.f);
    for (int p = 0; p < P_; p++) {
        float4 xv = ((const float4*)g_kv)[(size_t)(b * P_ + p) * 256 + tid];
        #pragma unroll
        for (int h = 0; h < H_; h++) {
            float a = sc[h * P_ + p];
            acc[h].x = fmaf(a, xv.x, acc[h].x); acc[h].y = fmaf(a, xv.y, acc[h].y);
            acc[h].z = fmaf(a, xv.z, acc[h].z); acc[h].w = fmaf(a, xv.w, acc[h].w);
        }
    }
    #pragma unroll
    for (int h = 0; h < H_; h++) {
        uint2 uh, ul;
        sp2(acc[h].x, acc[h].y, uh.x, ul.x);
        sp2(acc[h].z, acc[h].w, uh.y, ul.y);
        size_t o = (size_t)(h * B_ + b) * 256 + tid;
        ((uint2*)g_mx2_h)[o] = uh;
        ((uint2*)g_mx2_l)[o] = ul;
    }
}

__global__ __launch_bounds__(256) void k_logits(const float* __restrict__ w2,
                                                const float* __restrict__ b2,
                                                float* __restrict__ out) {
    int b = blockIdx.x, tid = threadIdx.x, w = tid >> 5, lane = tid & 31;
    const float* hrow = g_hid + (size_t)b * MH;
    for (int c = w; c < NC; c += 8) {
        float s = 0.f;
        for (int i = lane; i < MH; i += 32) s = fmaf(hrow[i], w2[(size_t)i * NC + c], s);
        #pragma unroll
        for (int o = 16; o; o >>= 1) s += __shfl_xor_sync(0xffffffffu, s, o);
        if (lane == 0) out[b * NC + c] = s + b2[c];
    }
}

// ---------------- launch ----------------
extern "C" void kernel_launch(void* const* d_in, const int* in_sizes, int n_in,
                              void* d_out, int out_size) {
    (void)in_sizes; (void)n_in; (void)out_size;
    const float* x    = (const float*)d_in[0];
    const float* chq  = (const float*)d_in[1];
    const float* clq  = (const float*)d_in[2];
    const float* chw  = (const float*)d_in[3];
    const float* chb  = (const float*)d_in[4];
    const float* chow = (const float*)d_in[5];
    const float* chob = (const float*)d_in[6];
    const float* tw   = (const float*)d_in[7];
    const float* tb   = (const float*)d_in[8];
    const float* tow  = (const float*)d_in[9];
    const float* tob  = (const float*)d_in[10];
    const float* qn_g = (const float*)d_in[11];
    const float* qn_b = (const float*)d_in[12];
    const float* cn_g = (const float*)d_in[13];
    const float* cn_b = (const float*)d_in[14];
    const float* pnc_g = (const float*)d_in[15];
    const float* pnc_b = (const float*)d_in[16];
    const float* pnp_g = (const float*)d_in[17];
    const float* pnp_b = (const float*)d_in[18];
    const float* pon_g = (const float*)d_in[19];
    const float* pon_b = (const float*)d_in[20];
    const float* w1 = (const float*)d_in[21];
    const float* b1 = (const float*)d_in[22];
    const float* w2 = (const float*)d_in[23];
    const float* b2 = (const float*)d_in[24];
    float* out = (float*)d_out;

    float *p_z, *p_p2, *p_hid;
    bf16 *mxh, *mxl, *plh, *pll, *m2h, *m2l, *p2h, *p2l, *lnh, *lnl;
    bf16 *wvh, *wvl, *cwh, *cwl, *w2h, *w2l, *toh, *tol, *w1h, *w1l;
    cudaGetSymbolAddress((void**)&p_z, g_z);
    cudaGetSymbolAddress((void**)&p_p2, g_p2);
    cudaGetSymbolAddress((void**)&p_hid, g_hid);
    cudaGetSymbolAddress((void**)&mxh, g_mx_h);     cudaGetSymbolAddress((void**)&mxl, g_mx_l);
    cudaGetSymbolAddress((void**)&plh, g_pooled_h); cudaGetSymbolAddress((void**)&pll, g_pooled_l);
    cudaGetSymbolAddress((void**)&m2h, g_mx2_h);    cudaGetSymbolAddress((void**)&m2l, g_mx2_l);
    cudaGetSymbolAddress((void**)&p2h, g_pooled2_h);cudaGetSymbolAddress((void**)&p2l, g_pooled2_l);
    cudaGetSymbolAddress((void**)&lnh, g_p2ln_h);   cudaGetSymbolAddress((void**)&lnl, g_p2ln_l);
    cudaGetSymbolAddress((void**)&wvh, g_wvT_h);    cudaGetSymbolAddress((void**)&wvl, g_wvT_l);
    cudaGetSymbolAddress((void**)&cwh, g_chowT_h);  cudaGetSymbolAddress((void**)&cwl, g_chowT_l);
    cudaGetSymbolAddress((void**)&w2h, g_wv2T_h);   cudaGetSymbolAddress((void**)&w2l, g_wv2T_l);
    cudaGetSymbolAddress((void**)&toh, g_towT_h);   cudaGetSymbolAddress((void**)&tol, g_towT_l);
    cudaGetSymbolAddress((void**)&w1h, g_w1T_h);    cudaGetSymbolAddress((void**)&w1l, g_w1T_l);

    cudaFuncSetAttribute(k_main, cudaFuncAttributeMaxDynamicSharedMemorySize, SMEM_MAIN);
    cudaFuncSetAttribute(k_mma, cudaFuncAttributeMaxDynamicSharedMemorySize, 3 * STG_B);
    const int MMS = 3 * STG_B;

    k_lnq<<<2, 256>>>(chq, clq, qn_g, qn_b, pnc_g, pnc_b);                  // 0
    k_qh<<<dim3(8, 2, 8), 128>>>(chw, tw);                                  // 1
    k_fold<<<dim3(512, 2), 128>>>(chw, chb, tw, tb);                        // 2
    k_main<<<dim3(P_, B_), 512, SMEM_MAIN>>>(x);                            // 3 <- captured
    k_trsplit<<<dim3(32, 32), 256>>>(chw, C3F, 2 * F_, wvh, wvl);           // 4
    k_mma<<<dim3(1, T_ / 128, H_), 256, MMS>>>(mxh, mxl, (long long)T_ * F_,
        wvh, wvl, (long long)64 * F_, chb + 2 * F_, 64,
        nullptr, plh, pll, F_, 64, 2);                                      // 5
    k_trsplit<<<dim3(32, 32), 256>>>(chow, F_, 0, cwh, cwl);                // 6
    k_mma<<<dim3(F_ / 64, T_ / 128, 1), 256, MMS>>>(plh, pll, 0,
        cwh, cwl, 0, chob, 0, p_z, nullptr, nullptr, F_, 0, 0);             // 7
    k_lnln<<<T_, 256>>>(cn_g, cn_b, pnp_g, pnp_b);                          // 8
    k_sc2mix<<<B_, 256>>>();                                                // 9
    k_trsplit<<<dim3(32, 32), 256>>>(tw, C3F, 2 * F_, w2h, w2l);            // 10
    k_mma<<<dim3(1, 1, H_), 256, MMS>>>(m2h, m2l, (long long)B_ * F_,
        w2h, w2l, (long long)64 * F_, tb + 2 * F_, 64,
        nullptr, p2h, p2l, F_, 64, 2);                                      // 11
    k_trsplit<<<dim3(32, 32), 256>>>(tow, F_, 0, toh, tol);                 // 12
    k_mma<<<dim3(F_ / 64, 1, 1), 256, MMS>>>(p2h, p2l, 0,
        toh, tol, 0, tob, 0, p_p2, nullptr, nullptr, F_, 0, 0);             // 13
    k_ln_split<<<B_, 256>>>(p_p2, pon_g, pon_b, lnh, lnl);                  // 14
    k_trsplit<<<dim3(32, 128), 256>>>(w1, MH, 0, w1h, w1l);                 // 15
    k_mma<<<dim3(MH / 64, 1, 1), 256, MMS>>>(lnh, lnl, 0,
        w1h, w1l, 0, b1, 0, p_hid, nullptr, nullptr, MH, 0, 1);             // 16
    k_logits<<<B_, 256>>>(w2, b2, out);                                     // 17
}